// round 9
// baseline (speedup 1.0000x reference)
#include <cuda_runtime.h>
#include <math.h>

// Constants
#define G_LEAK   0.1f
#define GBAR_NA  4.0f
#define GBAR_K   1.5f
#define GBAR_M   0.07f
#define E_NA     53.0f
#define E_K      (-107.0f)
#define E_LEAK   (-70.0f)
#define TAU_MAX  600.0f
// CURR_LEVEL / A_SOMA = 0.0005 / (pi * (70e-4)^2)
#define I_IN_ON  3.2481060598838624f

__device__ __forceinline__ float efun(float z) {
    // z/(exp(z)-1), Taylor 1 - z/2 near 0
    if (fabsf(z) < 1e-4f) return 1.0f - 0.5f * z;
    return __fdividef(z, __expf(z) - 1.0f);
}

__device__ __forceinline__ void hh_rhs(float V, float n, float m, float h, float p,
                                       float I_in,
                                       float& dV, float& dn, float& dm, float& dh, float& dp) {
    // rate functions (VT = -60 folded in)
    float a_m = 1.28f * efun(-0.25f * (V + 47.0f));
    float b_m = 1.40f * efun( 0.20f * (V + 20.0f));
    float a_h = 0.128f * __expf(-(V + 43.0f) * (1.0f / 18.0f));
    float b_h = __fdividef(4.0f, 1.0f + __expf(-0.2f * (V + 20.0f)));
    float a_n = 0.16f * efun(-0.20f * (V + 45.0f));
    float b_n = 0.5f * __expf(-(V + 50.0f) * 0.025f);

    float m3 = m * m * m;
    float n2 = n * n;
    float n4 = n2 * n2;

    float ek_v = E_K - V;
    dV = m3 * GBAR_NA * h * (E_NA - V)
       + n4 * GBAR_K * ek_v
       + GBAR_M * p * ek_v
       + G_LEAK * (E_LEAK - V)
       + I_in;

    // dx = a - (a+b)*x
    dn = fmaf(-(a_n + b_n), n, a_n);
    dm = fmaf(-(a_m + b_m), m, a_m);
    dh = fmaf(-(a_h + b_h), h, a_h);

    float v1 = V + 35.0f;
    float p_inf = __fdividef(1.0f, 1.0f + __expf(-0.1f * v1));
    float e = __expf(0.05f * v1);
    // tau_p = 600 / (3.3*e + 1/e);  dp = (p_inf - p) / tau_p
    float denom = fmaf(3.3f, e, __fdividef(1.0f, e));
    dp = (p_inf - p) * denom * (1.0f / TAU_MAX);
}

// Single-wave persistent kernel: 888 CTAs (148 SMs x 6 resident), grid-stride.
__global__ void __launch_bounds__(256)
hh_kernel(const int* __restrict__ t,
          const float4* __restrict__ V4,
          const float4* __restrict__ n4_,
          const float4* __restrict__ m4,
          const float4* __restrict__ h4,
          const float4* __restrict__ p4,
          float4* __restrict__ out,   // 5 contiguous segments of nvec float4 each
          int nvec)
{
    const int stride = gridDim.x * blockDim.x;
    const float I_in = (t[0] > 0) ? I_IN_ON : 0.0f;

    for (int i = blockIdx.x * blockDim.x + threadIdx.x; i < nvec; i += stride) {
        // Front-batch all 5 loads; next iteration's loads overlap these stores.
        float4 V = V4[i];
        float4 n = n4_[i];
        float4 m = m4[i];
        float4 h = h4[i];
        float4 p = p4[i];

        float4 dV, dn, dm, dh, dp;
        hh_rhs(V.x, n.x, m.x, h.x, p.x, I_in, dV.x, dn.x, dm.x, dh.x, dp.x);
        hh_rhs(V.y, n.y, m.y, h.y, p.y, I_in, dV.y, dn.y, dm.y, dh.y, dp.y);
        hh_rhs(V.z, n.z, m.z, h.z, p.z, I_in, dV.z, dn.z, dm.z, dh.z, dp.z);
        hh_rhs(V.w, n.w, m.w, h.w, p.w, I_in, dV.w, dn.w, dm.w, dh.w, dp.w);

        out[i]            = dV;
        out[nvec + i]     = dn;
        out[2 * nvec + i] = dm;
        out[3 * nvec + i] = dh;
        out[4 * nvec + i] = dp;
    }
}

extern "C" void kernel_launch(void* const* d_in, const int* in_sizes, int n_in,
                              void* d_out, int out_size) {
    const int*   t = (const int*)  d_in[0];
    const float* V = (const float*)d_in[1];
    const float* n = (const float*)d_in[2];
    const float* m = (const float*)d_in[3];
    const float* h = (const float*)d_in[4];
    const float* p = (const float*)d_in[5];

    int B = in_sizes[1];          // 8388608
    int nvec = B / 4;             // 2097152

    // One wave: 148 SMs x 6 CTAs/SM (40 regs -> 6 resident at 256 thr)
    dim3 block(256);
    dim3 grid(888);
    hh_kernel<<<grid, block>>>(t,
                               (const float4*)V, (const float4*)n, (const float4*)m,
                               (const float4*)h, (const float4*)p,
                               (float4*)d_out, nvec);
}

// round 10
// speedup vs baseline: 1.2424x; 1.2424x over previous
#include <cuda_runtime.h>
#include <math.h>

// Constants
#define G_LEAK   0.1f
#define GBAR_NA  4.0f
#define GBAR_K   1.5f
#define GBAR_M   0.07f
#define E_NA     53.0f
#define E_K      (-107.0f)
#define E_LEAK   (-70.0f)
#define TAU_MAX  600.0f
// CURR_LEVEL / A_SOMA = 0.0005 / (pi * (70e-4)^2)
#define I_IN_ON  3.2481060598838624f

__device__ __forceinline__ float efun(float z) {
    // z/(exp(z)-1), Taylor 1 - z/2 near 0
    if (fabsf(z) < 1e-4f) return 1.0f - 0.5f * z;
    return __fdividef(z, __expf(z) - 1.0f);
}

__device__ __forceinline__ void hh_rhs(float V, float n, float m, float h, float p,
                                       float I_in,
                                       float& dV, float& dn, float& dm, float& dh, float& dp) {
    // rate functions (VT = -60 folded in)
    float a_m = 1.28f * efun(-0.25f * (V + 47.0f));
    float b_m = 1.40f * efun( 0.20f * (V + 20.0f));
    float a_h = 0.128f * __expf(-(V + 43.0f) * (1.0f / 18.0f));
    float b_h = __fdividef(4.0f, 1.0f + __expf(-0.2f * (V + 20.0f)));
    float a_n = 0.16f * efun(-0.20f * (V + 45.0f));
    float b_n = 0.5f * __expf(-(V + 50.0f) * 0.025f);

    float m3 = m * m * m;
    float n2 = n * n;
    float n4 = n2 * n2;

    float ek_v = E_K - V;
    dV = m3 * GBAR_NA * h * (E_NA - V)
       + n4 * GBAR_K * ek_v
       + GBAR_M * p * ek_v
       + G_LEAK * (E_LEAK - V)
       + I_in;

    // dx = a - (a+b)*x
    dn = fmaf(-(a_n + b_n), n, a_n);
    dm = fmaf(-(a_m + b_m), m, a_m);
    dh = fmaf(-(a_h + b_h), h, a_h);

    float v1 = V + 35.0f;
    float p_inf = __fdividef(1.0f, 1.0f + __expf(-0.1f * v1));
    float e = __expf(0.05f * v1);
    // tau_p = 600 / (3.3*e + 1/e);  dp = (p_inf - p) / tau_p
    float denom = fmaf(3.3f, e, __fdividef(1.0f, e));
    dp = (p_inf - p) * denom * (1.0f / TAU_MAX);
}

__global__ void __launch_bounds__(256)
hh_kernel(const int* __restrict__ t,
          const float4* __restrict__ V4,
          const float4* __restrict__ n4_,
          const float4* __restrict__ m4,
          const float4* __restrict__ h4,
          const float4* __restrict__ p4,
          float4* __restrict__ out,   // 5 contiguous segments of B/4 float4 each
          int nvec)                   // = B/4
{
    int i = blockIdx.x * blockDim.x + threadIdx.x;
    if (i >= nvec) return;

    // Front-batch all 5 loads (MLP=5 float4 loads in flight)
    float4 V = V4[i];
    float4 n = n4_[i];
    float4 m = m4[i];
    float4 h = h4[i];
    float4 p = p4[i];

    float I_in = (t[0] > 0) ? I_IN_ON : 0.0f;

    float4 dV, dn, dm, dh, dp;
    hh_rhs(V.x, n.x, m.x, h.x, p.x, I_in, dV.x, dn.x, dm.x, dh.x, dp.x);
    hh_rhs(V.y, n.y, m.y, h.y, p.y, I_in, dV.y, dn.y, dm.y, dh.y, dp.y);
    hh_rhs(V.z, n.z, m.z, h.z, p.z, I_in, dV.z, dn.z, dm.z, dh.z, dp.z);
    hh_rhs(V.w, n.w, m.w, h.w, p.w, I_in, dV.w, dn.w, dm.w, dh.w, dp.w);

    out[i]            = dV;
    out[nvec + i]     = dn;
    out[2 * nvec + i] = dm;
    out[3 * nvec + i] = dh;
    out[4 * nvec + i] = dp;
}

extern "C" void kernel_launch(void* const* d_in, const int* in_sizes, int n_in,
                              void* d_out, int out_size) {
    const int*   t = (const int*)  d_in[0];
    const float* V = (const float*)d_in[1];
    const float* n = (const float*)d_in[2];
    const float* m = (const float*)d_in[3];
    const float* h = (const float*)d_in[4];
    const float* p = (const float*)d_in[5];

    int B = in_sizes[1];          // 8388608
    int nvec = B / 4;             // 2097152

    dim3 block(256);
    dim3 grid((nvec + block.x - 1) / block.x);
    hh_kernel<<<grid, block>>>(t,
                               (const float4*)V, (const float4*)n, (const float4*)m,
                               (const float4*)h, (const float4*)p,
                               (float4*)d_out, nvec);
}